// round 4
// baseline (speedup 1.0000x reference)
#include <cuda_runtime.h>
#include <math.h>

// Fixed problem shape
#define BB 8
#define NN 32768
#define CC 4
#define MM 11
#define HALO (MM - 1)          // 10

#define TILE 256
#define THREADS 256
#define NTILES (NN / TILE)     // 128
#define NSAMP (TILE + HALO)    // 266 samples per channel row
#define SROW 273               // float4 stride per channel row; 273 % 8 == 1 -> conflict-free

typedef unsigned long long u64;

__device__ __forceinline__ u64 pk(float x, float y) {
    u64 r; asm("mov.b64 %0, {%1, %2};" : "=l"(r) : "f"(x), "f"(y)); return r;
}
__device__ __forceinline__ void unpk(u64 v, float& x, float& y) {
    asm("mov.b64 {%0, %1}, %2;" : "=f"(x), "=f"(y) : "l"(v));
}
__device__ __forceinline__ u64 dup2(float x) { return pk(x, x); }
__device__ __forceinline__ u64 ffma2(u64 a, u64 b, u64 c) {
    u64 d; asm("fma.rn.f32x2 %0, %1, %2, %3;" : "=l"(d) : "l"(a), "l"(b), "l"(c)); return d;
}

// out[b,c,n] = sum_{j=0..10} z[n-10+j] * P_{c,j}(|z[n-10+j]|)
// P_{c,j}(a) = w0 + w1 a + w2 a^2 + w3 a^3 + w4 a^4,  w_d = W[c, d*11 + j]

__global__ __launch_bounds__(THREADS)
void gmp_fir_kernel(const float* __restrict__ x,
                    const float* __restrict__ W,
                    float* __restrict__ out)
{
    __shared__ float4 s_d[CC * SROW];        // (re, im, a, a^2), channel-major
    __shared__ float  s_W2[CC * MM * 8];     // [c][j][8]: d=0..4 at offsets 0..4

    const int tile = blockIdx.x % NTILES;
    const int b    = blockIdx.x / NTILES;
    const int n0   = tile * TILE;

    // Weight transpose: W[c, d*11+j] -> s_W2[(c*11+j)*8 + d]
    for (int i = threadIdx.x; i < CC * 5 * MM; i += THREADS) {
        const int c = i / 55, r = i % 55, d = r / MM, j = r % MM;
        s_W2[(c * MM + j) * 8 + d] = W[i];
    }

    // Stage tile + halo. One float4 = (re,im) of channels {2cp, 2cp+1} at one n.
    const float4* x4 = (const float4*)x + (size_t)b * NN * 2;
    for (int i = threadIdx.x; i < NSAMP * 2; i += THREADS) {
        const int nl = i >> 1, cp = i & 1;
        const int n  = n0 - HALO + nl;
        float4 v = make_float4(0.f, 0.f, 0.f, 0.f);
        if (n >= 0) v = x4[(size_t)n * 2 + cp];
        const float q0 = v.x * v.x + v.y * v.y;
        const float q1 = v.z * v.z + v.w * v.w;
        s_d[(2 * cp)     * SROW + nl] = make_float4(v.x, v.y, sqrtf(q0), q0);
        s_d[(2 * cp + 1) * SROW + nl] = make_float4(v.z, v.w, sqrtf(q1), q1);
    }
    __syncthreads();

    // Thread -> channel c = tid&3, consecutive outputs nl0..nl0+3.
    const int c   = threadIdx.x & (CC - 1);
    const int nl0 = (threadIdx.x >> 2) << 2;
    const float4* row  = s_d + c * SROW + nl0;     // row[u] = sample n0 + nl0 + u - 10
    const float*  wrow = s_W2 + c * (MM * 8);

    float4 sv[MM + 3];
    u64    zp[MM + 3];
    #pragma unroll
    for (int u = 0; u < 3; ++u) { sv[u] = row[u]; zp[u] = pk(sv[u].x, sv[u].y); }

    u64 acc0 = 0ull, acc1 = 0ull, acc2 = 0ull, acc3 = 0ull;

    #pragma unroll
    for (int j = 0; j < MM; ++j) {
        sv[j + 3] = row[j + 3];
        zp[j + 3] = pk(sv[j + 3].x, sv[j + 3].y);

        const float4 wv  = *(const float4*)(wrow + j * 8);   // w0..w3
        const float  w4s = wrow[j * 8 + 4];
        const u64 W0 = dup2(wv.x), W1 = dup2(wv.y), W2 = dup2(wv.z),
                  W3 = dup2(wv.w), W4 = dup2(w4s);

        // pair A: outputs k=0,1 use samples u=j, j+1
        {
            const u64 aa = pk(sv[j].z, sv[j + 1].z);
            const u64 a2 = pk(sv[j].w, sv[j + 1].w);
            u64 t = ffma2(aa, W1, W0);
            u64 u_ = ffma2(aa, W3, W2);
            u_ = ffma2(a2, W4, u_);
            const u64 p = ffma2(a2, u_, t);
            float p0, p1; unpk(p, p0, p1);
            acc0 = ffma2(zp[j],     dup2(p0), acc0);
            acc1 = ffma2(zp[j + 1], dup2(p1), acc1);
        }
        // pair B: outputs k=2,3 use samples u=j+2, j+3
        {
            const u64 aa = pk(sv[j + 2].z, sv[j + 3].z);
            const u64 a2 = pk(sv[j + 2].w, sv[j + 3].w);
            u64 t = ffma2(aa, W1, W0);
            u64 u_ = ffma2(aa, W3, W2);
            u_ = ffma2(a2, W4, u_);
            const u64 p = ffma2(a2, u_, t);
            float p0, p1; unpk(p, p0, p1);
            acc2 = ffma2(zp[j + 2], dup2(p0), acc2);
            acc3 = ffma2(zp[j + 3], dup2(p1), acc3);
        }
    }

    float2* o2 = (float2*)out + ((size_t)b * NN + n0) * CC;
    float r0, i0;
    unpk(acc0, r0, i0); o2[(nl0 + 0) * CC + c] = make_float2(r0, i0);
    unpk(acc1, r0, i0); o2[(nl0 + 1) * CC + c] = make_float2(r0, i0);
    unpk(acc2, r0, i0); o2[(nl0 + 2) * CC + c] = make_float2(r0, i0);
    unpk(acc3, r0, i0); o2[(nl0 + 3) * CC + c] = make_float2(r0, i0);
}

extern "C" void kernel_launch(void* const* d_in, const int* in_sizes, int n_in,
                              void* d_out, int out_size)
{
    const float* x = (const float*)d_in[0];   // [B,N,C,2] fp32
    const float* W = (const float*)d_in[1];   // [C, 55]   fp32
    float* out = (float*)d_out;               // [B,N,C,2] fp32
    (void)in_sizes; (void)n_in; (void)out_size;

    gmp_fir_kernel<<<BB * NTILES, THREADS>>>(x, W, out);
}

// round 5
// speedup vs baseline: 1.3047x; 1.3047x over previous
#include <cuda_runtime.h>
#include <math.h>

// Fixed problem shape
#define BB 8
#define NN 32768
#define CC 4
#define MM 11
#define HALO (MM - 1)           // 10

#define THREADS 128
#define KPT 8                   // consecutive outputs per thread
#define TILE 256                // n per block = THREADS*KPT/CC
#define NTILES (NN / TILE)      // 128
#define NSAMP (TILE + HALO)     // 266 samples per channel

// channel-minor sample words w = r*4 + c, skewed to kill stride-32 conflicts
__device__ __forceinline__ int skew(int w) { return w + ((w >> 5) << 2); }
#define SMAX (1063 + 4 * (1063 >> 5) + 1)   // 1196 float4 slots

typedef unsigned long long u64;

__device__ __forceinline__ u64 pk(float x, float y) {
    u64 r; asm("mov.b64 %0, {%1, %2};" : "=l"(r) : "f"(x), "f"(y)); return r;
}
__device__ __forceinline__ void unpk(u64 v, float& x, float& y) {
    asm("mov.b64 {%0, %1}, %2;" : "=f"(x), "=f"(y) : "l"(v));
}
__device__ __forceinline__ u64 ffma2(u64 a, u64 b, u64 c) {
    u64 d; asm("fma.rn.f32x2 %0, %1, %2, %3;" : "=l"(d) : "l"(a), "l"(b), "l"(c)); return d;
}

// out[b,c,n] = sum_j z[n-10+j] * P_{c,j}(|z|),  P = w0+w1 a+w2 a^2+w3 a^3+w4 a^4

__global__ __launch_bounds__(THREADS)
void gmp_fir_kernel(const float* __restrict__ x,
                    const float* __restrict__ W,
                    float* __restrict__ out)
{
    __shared__ float4 s_d[SMAX];             // (re, im, a, a^2) at skew(r*4+c)
    __shared__ float2 s_W2[CC * MM * 6];     // [c][j][6]: (w_d, w_d) duplicated pairs

    const int tile = blockIdx.x % NTILES;
    const int b    = blockIdx.x / NTILES;
    const int n0   = tile * TILE;

    // Weights, duplicated into lane pairs: W[c, d*11+j] -> s_W2[(c*11+j)*6 + d]
    for (int i = threadIdx.x; i < CC * 5 * MM; i += THREADS) {
        const int c = i / 55, r = i % 55, d = r / MM, j = r % MM;
        const float w = W[i];
        s_W2[(c * MM + j) * 6 + d] = make_float2(w, w);
    }

    // Stage tile + halo: one float4 global load = channels {2cp,2cp+1} at sample nl
    const float4* x4 = (const float4*)x + (size_t)b * NN * 2;
    for (int i = threadIdx.x; i < NSAMP * 2; i += THREADS) {
        const int nl = i >> 1, cp = i & 1;
        const int n  = n0 - HALO + nl;
        float4 v = make_float4(0.f, 0.f, 0.f, 0.f);
        if (n >= 0) v = x4[(size_t)n * 2 + cp];
        const float q0 = v.x * v.x + v.y * v.y;
        const float q1 = v.z * v.z + v.w * v.w;
        s_d[skew(nl * 4 + 2 * cp)]     = make_float4(v.x, v.y, sqrtf(q0), q0);
        s_d[skew(nl * 4 + 2 * cp + 1)] = make_float4(v.z, v.w, sqrtf(q1), q1);
    }
    __syncthreads();

    // Thread -> channel c, 8 consecutive outputs nl0..nl0+7
    const int c   = threadIdx.x & (CC - 1);
    const int nl0 = (threadIdx.x >> 2) * KPT;
    const int w0i = nl0 * 4 + c;                 // word index of sample u=0 (row coords)
    const float2* wrow = s_W2 + c * (MM * 6);

    float4 sv[8];                                // sliding window, slot u&7
    #pragma unroll
    for (int u = 0; u < 7; ++u) sv[u] = s_d[skew(w0i + u * 4)];

    u64 accr[4], acci[4];
    #pragma unroll
    for (int p = 0; p < 4; ++p) { accr[p] = 0ull; acci[p] = 0ull; }

    #pragma unroll
    for (int j = 0; j < MM; ++j) {
        sv[(j + 7) & 7] = s_d[skew(w0i + (j + 7) * 4)];

        // 5 duplicated weight pairs: one LDS.128 (w0,w1,w2,w3 as 2 u64) + one LDS.64
        const float4 wAB = *(const float4*)(wrow + j * 6);      // (w0,w0,w1,w1)... NO:
        // float4 here = two float2 pairs: (w0.x,w0.y | w1.x,w1.y) = ((w0,w0),(w1,w1))
        const float4 wCD = *(const float4*)(wrow + j * 6 + 2);  // ((w2,w2),(w3,w3))
        const float2 wE  = wrow[j * 6 + 4];                     // (w4,w4)
        const u64 W0 = *(const u64*)&wAB.x;
        const u64 W1 = *(const u64*)&wAB.z;
        const u64 W2 = *(const u64*)&wCD.x;
        const u64 W3 = *(const u64*)&wCD.z;
        const u64 W4 = *(const u64*)&wE;

        #pragma unroll
        for (int p = 0; p < 4; ++p) {
            const float4 A = sv[(j + 2 * p) & 7];
            const float4 Bv = sv[(j + 2 * p + 1) & 7];
            const u64 aa = pk(A.z, Bv.z);
            const u64 a2 = pk(A.w, Bv.w);
            u64 t = ffma2(aa, W1, W0);
            u64 v = ffma2(aa, W3, W2);
            v = ffma2(a2, W4, v);
            const u64 P = ffma2(a2, v, t);       // (p_k, p_{k+1})
            const u64 re2 = pk(A.x, Bv.x);
            const u64 im2 = pk(A.y, Bv.y);
            accr[p] = ffma2(re2, P, accr[p]);
            acci[p] = ffma2(im2, P, acci[p]);
        }
    }

    float2* o2 = (float2*)out + ((size_t)b * NN + n0) * CC;
    #pragma unroll
    for (int p = 0; p < 4; ++p) {
        float r0, r1, i0, i1;
        unpk(accr[p], r0, r1);
        unpk(acci[p], i0, i1);
        o2[(nl0 + 2 * p)     * CC + c] = make_float2(r0, i0);
        o2[(nl0 + 2 * p + 1) * CC + c] = make_float2(r1, i1);
    }
}

extern "C" void kernel_launch(void* const* d_in, const int* in_sizes, int n_in,
                              void* d_out, int out_size)
{
    const float* x = (const float*)d_in[0];   // [B,N,C,2] fp32
    const float* W = (const float*)d_in[1];   // [C, 55]   fp32
    float* out = (float*)d_out;               // [B,N,C,2] fp32
    (void)in_sizes; (void)n_in; (void)out_size;

    gmp_fir_kernel<<<BB * NTILES, THREADS>>>(x, W, out);
}

// round 6
// speedup vs baseline: 1.3275x; 1.0175x over previous
#include <cuda_runtime.h>
#include <math.h>

// Fixed problem shape
#define BB 8
#define NN 32768
#define CC 4
#define MM 11
#define HALO 10

#define THREADS 128
#define KPT 8
#define TILE 256                 // outputs(n) per block
#define NTILES (NN / TILE)       // 128
#define NSAMP (TILE + HALO)      // 266 samples per channel
#define PROW 305                 // skewed row capacity per channel (266+33 fits)

typedef unsigned long long u64;

// skewed per-channel sample index (conflict-free for the lane patterns below)
__device__ __forceinline__ int sidx(int c, int u) { return c * PROW + u + (u >> 3); }

__device__ __forceinline__ u64 dup2(float x) {
    u64 r; asm("mov.b64 %0, {%1, %1};" : "=l"(r) : "f"(x)); return r;
}
__device__ __forceinline__ void unpk(u64 v, float& x, float& y) {
    asm("mov.b64 {%0, %1}, %2;" : "=f"(x), "=f"(y) : "l"(v));
}
__device__ __forceinline__ u64 ffma2(u64 a, u64 b, u64 c) {
    u64 d; asm("fma.rn.f32x2 %0, %1, %2, %3;" : "=l"(d) : "l"(a), "l"(b), "l"(c)); return d;
}
__device__ __forceinline__ u64 fmul2(u64 a, u64 b) {
    u64 d; asm("mul.rn.f32x2 %0, %1, %2;" : "=l"(d) : "l"(a), "l"(b)); return d;
}

// out[b,c,n] = sum_{j=0..10} z[n-10+j] * P_{c,j}(|z|),  P = w0+w1 a+w2 a^2+w3 a^3+w4 a^4

__global__ __launch_bounds__(THREADS, 7)
void gmp_fir_kernel(const float* __restrict__ x,
                    const float* __restrict__ W,
                    float* __restrict__ out)
{
    __shared__ float2 s_z[CC * PROW];     // (re_u, im_u)
    __shared__ float2 s_p[CC * PROW];     // (a_u, a_{u+1})
    __shared__ float2 s_W2[CC * MM * 6];  // duplicated weight pairs, stride 6 (16B align)

    const int tile = blockIdx.x % NTILES;
    const int b    = blockIdx.x / NTILES;
    const int n0   = tile * TILE;

    // Weights: W[c, d*11+j] -> s_W2[(c*11+j)*6 + d] = (w, w)
    for (int i = threadIdx.x; i < CC * 5 * MM; i += THREADS) {
        const int c = i / 55, r = i % 55, d = r / MM, j = r % MM;
        const float w = W[i];
        s_W2[(c * MM + j) * 6 + d] = make_float2(w, w);
    }

    // Stage tile + halo. One float4 = (re,im) of channels {2cp,2cp+1} at sample nl.
    const float4* x4 = (const float4*)x + (size_t)b * NN * 2;
    for (int i = threadIdx.x; i < NSAMP * 2; i += THREADS) {
        const int nl = i >> 1, cp = i & 1;
        const int n  = n0 - HALO + nl;
        float4 v = make_float4(0.f, 0.f, 0.f, 0.f);
        if (n >= 0) v = x4[(size_t)n * 2 + cp];
        const float a0 = sqrtf(v.x * v.x + v.y * v.y);
        const float a1 = sqrtf(v.z * v.z + v.w * v.w);
        const int c0 = 2 * cp, c1 = c0 + 1;
        s_z[sidx(c0, nl)] = make_float2(v.x, v.y);
        s_z[sidx(c1, nl)] = make_float2(v.z, v.w);
        s_p[sidx(c0, nl)].x = a0;                 // pair (a_nl, a_{nl+1}): this sample is .x here
        s_p[sidx(c1, nl)].x = a1;
        if (nl >= 1) {
            s_p[sidx(c0, nl - 1)].y = a0;         // ...and .y of the previous pair
            s_p[sidx(c1, nl - 1)].y = a1;
        }
    }
    __syncthreads();

    // Warp = channel; lane l owns 8 consecutive outputs nl0 = 8l .. 8l+7.
    const int c = threadIdx.x >> 5;
    const int l = threadIdx.x & 31;
    const int base = c * PROW + 9 * l;            // sidx(c, 8l + off) = base + off + (off>>3)
    #define ZV(off) (*(const u64*)&s_z[base + (off) + ((off) >> 3)])
    #define PV(off) (*(const u64*)&s_p[base + (off) + ((off) >> 3)])

    const float2* wrow = s_W2 + c * (MM * 6);

    u64 zv[8], pv[8];
    #pragma unroll
    for (int u = 0; u < 7; ++u) zv[u] = ZV(u);
    #pragma unroll
    for (int u = 0; u < 6; ++u) pv[u] = PV(u);

    u64 acc[KPT];
    #pragma unroll
    for (int k = 0; k < KPT; ++k) acc[k] = 0ull;

    #pragma unroll
    for (int j = 0; j < MM; ++j) {
        zv[(j + 7) & 7] = ZV(j + 7);
        pv[(j + 6) & 7] = PV(j + 6);

        const u64 W0 = *(const u64*)&wrow[j * 6 + 0];
        const u64 W1 = *(const u64*)&wrow[j * 6 + 1];
        const u64 W2 = *(const u64*)&wrow[j * 6 + 2];
        const u64 W3 = *(const u64*)&wrow[j * 6 + 3];
        const u64 W4 = *(const u64*)&wrow[j * 6 + 4];

        #pragma unroll
        for (int p = 0; p < 4; ++p) {
            const int u = j + 2 * p;
            const u64 aa = pv[u & 7];             // (a_u, a_{u+1}) straight from window
            const u64 a2 = fmul2(aa, aa);
            u64 t  = ffma2(aa, W1, W0);
            u64 v2 = ffma2(aa, W3, W2);
            v2 = ffma2(a2, W4, v2);
            const u64 P = ffma2(a2, v2, t);       // (p_u, p_{u+1})
            float p0, p1; unpk(P, p0, p1);
            acc[2 * p]     = ffma2(zv[u & 7],       dup2(p0), acc[2 * p]);
            acc[2 * p + 1] = ffma2(zv[(u + 1) & 7], dup2(p1), acc[2 * p + 1]);
        }
    }

    // Results -> smem (reuse s_z), then coalesced global store.
    __syncthreads();
    #pragma unroll
    for (int k = 0; k < KPT; ++k) {
        float r0, i0; unpk(acc[k], r0, i0);
        s_z[base + k] = make_float2(r0, i0);      // sidx(c, 8l+k), k<8 -> no skew step
    }
    __syncthreads();

    float2* o2 = (float2*)out + ((size_t)b * NN + n0) * CC;
    #pragma unroll
    for (int t = 0; t < (TILE * CC) / THREADS; ++t) {
        const int i = threadIdx.x + t * THREADS;
        o2[i] = s_z[sidx(i & 3, i >> 2)];
    }
    #undef ZV
    #undef PV
}

extern "C" void kernel_launch(void* const* d_in, const int* in_sizes, int n_in,
                              void* d_out, int out_size)
{
    const float* x = (const float*)d_in[0];   // [B,N,C,2] fp32
    const float* W = (const float*)d_in[1];   // [C, 55]   fp32
    float* out = (float*)d_out;               // [B,N,C,2] fp32
    (void)in_sizes; (void)n_in; (void)out_size;

    gmp_fir_kernel<<<BB * NTILES, THREADS>>>(x, W, out);
}